// round 14
// baseline (speedup 1.0000x reference)
#include <cuda_runtime.h>
#include <math.h>

// Problem constants
#define B 64
#define S 4096
#define H 256
#define CHUNKS 16
#define ROWS_PER_CHUNK (S / CHUNKS)             // 256
#define WARPS 4
#define ROWS_PER_WARP (ROWS_PER_CHUNK / WARPS)  // 64 -> 2 ballot words
#define NEGC 1e30f
#define BB 4                                    // batches per tail CTA

// Scratch: per (b, chunk): 256 acc + m + l (258 floats)
__device__ float g_scratch[B * CHUNKS * (H + 2)];

// ---------------------------------------------------------------------------
// Kernel 1: streaming online-softmax partials with mask skipping,
// 4 valid rows per iteration. (unchanged from R13 — confirmed config)
// grid = (CHUNKS, B) = 1024 CTAs, block = 128, min 7 CTAs/SM.
// ---------------------------------------------------------------------------
__global__ void __launch_bounds__(128, 7)
attn_partial_kernel(const float* __restrict__ inp,
                    const float* __restrict__ mask,
                    const float* __restrict__ query,
                    const float* __restrict__ W)
{
    const int chunk = blockIdx.x;
    const int b     = blockIdx.y;
    const int tid   = threadIdx.x;
    const int w     = tid >> 5;
    const int lane  = tid & 31;

    // Warm W (512 KB = 4096 lines) into L2 for the tail kernel.
    if (chunk == 0) {
        const int line = b * 128 + tid;
        if (line < (H * 2 * H * 4) / 128) {
            const char* p = reinterpret_cast<const char*>(W) + (size_t)line * 128;
            asm volatile("prefetch.global.L2 [%0];" :: "l"(p));
        }
    }

    float q[8];
    {
        const float4 q0 = *reinterpret_cast<const float4*>(query + (size_t)b * H + lane * 4);
        const float4 q1 = *reinterpret_cast<const float4*>(query + (size_t)b * H + 128 + lane * 4);
        q[0]=q0.x; q[1]=q0.y; q[2]=q0.z; q[3]=q0.w;
        q[4]=q1.x; q[5]=q1.y; q[6]=q1.z; q[7]=q1.w;
    }

    float m = -3.0e38f;
    float l = 0.0f;
    float acc[8];
    #pragma unroll
    for (int i = 0; i < 8; i++) acc[i] = 0.0f;

    const int s_base = chunk * ROWS_PER_CHUNK + w * ROWS_PER_WARP;
    const float* rowbase = inp  + ((size_t)b * S + s_base) * H + lane * 4;
    const float* mrow    = mask + (size_t)b * S + s_base;

    #pragma unroll
    for (int half = 0; half < 2; half++) {
        const float mkv = __ldcs(&mrow[half * 32 + lane]);
        unsigned bits = __ballot_sync(0xffffffffu, mkv > 0.5f);
        const float* hb = rowbase + (size_t)(half * 32) * H;

        while (bits) {
            const int r0 = __ffs(bits) - 1; bits &= bits - 1;
            const bool h1 = bits != 0;
            const int r1 = h1 ? (__ffs(bits) - 1) : r0; if (h1) bits &= bits - 1;
            const bool h2 = bits != 0;
            const int r2 = h2 ? (__ffs(bits) - 1) : r0; if (h2) bits &= bits - 1;
            const bool h3 = bits != 0;
            const int r3 = h3 ? (__ffs(bits) - 1) : r0; if (h3) bits &= bits - 1;

            const float* p0 = hb + (size_t)r0 * H;
            const float* p1 = hb + (size_t)r1 * H;
            const float* p2 = hb + (size_t)r2 * H;
            const float* p3 = hb + (size_t)r3 * H;
            const float4 a0 = __ldcs(reinterpret_cast<const float4*>(p0));
            const float4 a1 = __ldcs(reinterpret_cast<const float4*>(p0 + 128));
            const float4 b0 = __ldcs(reinterpret_cast<const float4*>(p1));
            const float4 b1 = __ldcs(reinterpret_cast<const float4*>(p1 + 128));
            const float4 c0 = __ldcs(reinterpret_cast<const float4*>(p2));
            const float4 c1 = __ldcs(reinterpret_cast<const float4*>(p2 + 128));
            const float4 e0 = __ldcs(reinterpret_cast<const float4*>(p3));
            const float4 e1 = __ldcs(reinterpret_cast<const float4*>(p3 + 128));

            float d0 = q[0]*a0.x + q[1]*a0.y + q[2]*a0.z + q[3]*a0.w
                     + q[4]*a1.x + q[5]*a1.y + q[6]*a1.z + q[7]*a1.w;
            float d1 = q[0]*b0.x + q[1]*b0.y + q[2]*b0.z + q[3]*b0.w
                     + q[4]*b1.x + q[5]*b1.y + q[6]*b1.z + q[7]*b1.w;
            float d2 = q[0]*c0.x + q[1]*c0.y + q[2]*c0.z + q[3]*c0.w
                     + q[4]*c1.x + q[5]*c1.y + q[6]*c1.z + q[7]*c1.w;
            float d3 = q[0]*e0.x + q[1]*e0.y + q[2]*e0.z + q[3]*e0.w
                     + q[4]*e1.x + q[5]*e1.y + q[6]*e1.z + q[7]*e1.w;

            #pragma unroll
            for (int off = 16; off > 0; off >>= 1) {
                d0 += __shfl_xor_sync(0xffffffffu, d0, off);
                d1 += __shfl_xor_sync(0xffffffffu, d1, off);
                d2 += __shfl_xor_sync(0xffffffffu, d2, off);
                d3 += __shfl_xor_sync(0xffffffffu, d3, off);
            }

            const float sc0 = d0;
            const float sc1 = h1 ? d1 : -3.0e38f;
            const float sc2 = h2 ? d2 : -3.0e38f;
            const float sc3 = h3 ? d3 : -3.0e38f;
            const float mn  = fmaxf(fmaxf(m, fmaxf(sc0, sc1)), fmaxf(sc2, sc3));
            const float alpha = __expf(m   - mn);
            const float p0e   = __expf(sc0 - mn);
            const float p1e   = __expf(sc1 - mn);
            const float p2e   = __expf(sc2 - mn);
            const float p3e   = __expf(sc3 - mn);
            l = l * alpha + p0e + p1e + p2e + p3e;
            acc[0] = acc[0]*alpha + p0e*a0.x + p1e*b0.x + p2e*c0.x + p3e*e0.x;
            acc[1] = acc[1]*alpha + p0e*a0.y + p1e*b0.y + p2e*c0.y + p3e*e0.y;
            acc[2] = acc[2]*alpha + p0e*a0.z + p1e*b0.z + p2e*c0.z + p3e*e0.z;
            acc[3] = acc[3]*alpha + p0e*a0.w + p1e*b0.w + p2e*c0.w + p3e*e0.w;
            acc[4] = acc[4]*alpha + p0e*a1.x + p1e*b1.x + p2e*c1.x + p3e*e1.x;
            acc[5] = acc[5]*alpha + p0e*a1.y + p1e*b1.y + p2e*c1.y + p3e*e1.y;
            acc[6] = acc[6]*alpha + p0e*a1.z + p1e*b1.z + p2e*c1.z + p3e*e1.z;
            acc[7] = acc[7]*alpha + p0e*a1.w + p1e*b1.w + p2e*c1.w + p3e*e1.w;
            m = mn;
        }
    }

    __shared__ float sm_m[WARPS];
    __shared__ float sm_l[WARPS];
    __shared__ float sm_acc[WARPS * H];

    if (lane == 0) { sm_m[w] = m; sm_l[w] = l; }
    #pragma unroll
    for (int i = 0; i < 4; i++) {
        sm_acc[w * H + lane * 4 + i]       = acc[i];
        sm_acc[w * H + 128 + lane * 4 + i] = acc[4 + i];
    }
    __syncthreads();

    float mb = sm_m[0];
    #pragma unroll
    for (int ww = 1; ww < WARPS; ww++) mb = fmaxf(mb, sm_m[ww]);

    float lb = 0.0f, ab0 = 0.0f, ab1 = 0.0f;
    #pragma unroll
    for (int ww = 0; ww < WARPS; ww++) {
        const float e = __expf(sm_m[ww] - mb);
        lb  += sm_l[ww] * e;
        ab0 += sm_acc[ww * H + tid] * e;
        ab1 += sm_acc[ww * H + tid + 128] * e;
    }

    float* dst = g_scratch + ((size_t)(b * CHUNKS + chunk)) * (H + 2);
    dst[tid]       = ab0;
    dst[tid + 128] = ab1;
    if (tid == 0) { dst[H] = mb; dst[H + 1] = lb; }
}

// ---------------------------------------------------------------------------
// Kernel 2: batch-blocked combine + projection.
// grid = (B/BB, 8) = 128 CTAs, block = 256 (8 warps).
// Each CTA: phase A builds conc for BB=4 batches; phase B loads each W row
// ONCE and dots it against all 4 conc vectors (W L2 traffic /4, FMA/load x4).
// ---------------------------------------------------------------------------
__global__ void __launch_bounds__(256)
combine_proj_kernel(const float* __restrict__ query,
                    const float* __restrict__ W,
                    const float* __restrict__ bias,
                    float* __restrict__ out)
{
    const int b0   = blockIdx.x * BB;
    const int by   = blockIdx.y;
    const int t    = threadIdx.x;
    const int w    = t >> 5;
    const int lane = t & 31;

    __shared__ float conc[BB][2 * H];

    const int j_base = by * 32 + w * 4;

    // Prefetch W rows for the first j-pair into registers (overlaps phase A)
    const float4* w0p = reinterpret_cast<const float4*>(W + (size_t)(j_base + 0) * (2 * H)) + lane;
    const float4* w1p = reinterpret_cast<const float4*>(W + (size_t)(j_base + 1) * (2 * H)) + lane;
    float4 w0r[4], w1r[4];
    #pragma unroll
    for (int k = 0; k < 4; k++) { w0r[k] = w0p[k * 32]; w1r[k] = w1p[k * 32]; }

    // --- Phase A: combine partials for element h=t, for each of BB batches ---
    #pragma unroll
    for (int bq = 0; bq < BB; bq++) {
        const int b = b0 + bq;
        const float* base = g_scratch + (size_t)b * CHUNKS * (H + 2);

        float m = -3.0e38f;
        float msv[CHUNKS];
        #pragma unroll
        for (int c = 0; c < CHUNKS; c++) {
            msv[c] = base[c * (H + 2) + H];
            m = fmaxf(m, msv[c]);
        }

        float l = 0.0f, a = 0.0f;
        #pragma unroll
        for (int c = 0; c < CHUNKS; c++) {
            const float e = __expf(msv[c] - m);
            l += base[c * (H + 2) + H + 1] * e;
            a += base[c * (H + 2) + t] * e;
        }

        const float ext = a / l;
        if (by == 0) out[(size_t)b * H + t] = ext;   // extracted_msg (once)
        conc[bq][t]     = query[(size_t)b * H + t];
        conc[bq][H + t] = ext;
    }
    __syncthreads();

    // --- Phase B: each warp does 4 j's; every W row dotted vs 4 batches ---
    // pair 0 (prefetched W regs)
    {
        float s0[BB], s1[BB];
        #pragma unroll
        for (int bq = 0; bq < BB; bq++) { s0[bq] = 0.0f; s1[bq] = 0.0f; }
        #pragma unroll
        for (int k = 0; k < 4; k++) {
            const int ci = (k * 32 + lane) * 4;
            #pragma unroll
            for (int bq = 0; bq < BB; bq++) {
                const float4 cv = *reinterpret_cast<const float4*>(&conc[bq][ci]);
                s0[bq] += w0r[k].x*cv.x + w0r[k].y*cv.y + w0r[k].z*cv.z + w0r[k].w*cv.w;
                s1[bq] += w1r[k].x*cv.x + w1r[k].y*cv.y + w1r[k].z*cv.z + w1r[k].w*cv.w;
            }
        }
        #pragma unroll
        for (int off = 16; off > 0; off >>= 1) {
            #pragma unroll
            for (int bq = 0; bq < BB; bq++) {
                s0[bq] += __shfl_xor_sync(0xffffffffu, s0[bq], off);
                s1[bq] += __shfl_xor_sync(0xffffffffu, s1[bq], off);
            }
        }
        if (lane == 0) {
            const float bj0 = bias[j_base + 0];
            const float bj1 = bias[j_base + 1];
            #pragma unroll
            for (int bq = 0; bq < BB; bq++) {
                float* outc = out + (size_t)B * H + (size_t)(b0 + bq) * H;
                outc[j_base + 0] = s0[bq] + bj0;
                outc[j_base + 1] = s1[bq] + bj1;
            }
        }
    }
    // pair 1
    {
        const int j0 = j_base + 2;
        const int j1 = j_base + 3;
        const float4* w2p = reinterpret_cast<const float4*>(W + (size_t)j0 * (2 * H)) + lane;
        const float4* w3p = reinterpret_cast<const float4*>(W + (size_t)j1 * (2 * H)) + lane;

        float s0[BB], s1[BB];
        #pragma unroll
        for (int bq = 0; bq < BB; bq++) { s0[bq] = 0.0f; s1[bq] = 0.0f; }
        #pragma unroll
        for (int k = 0; k < 4; k++) {
            const float4 wv0 = w2p[k * 32];
            const float4 wv1 = w3p[k * 32];
            const int ci = (k * 32 + lane) * 4;
            #pragma unroll
            for (int bq = 0; bq < BB; bq++) {
                const float4 cv = *reinterpret_cast<const float4*>(&conc[bq][ci]);
                s0[bq] += wv0.x*cv.x + wv0.y*cv.y + wv0.z*cv.z + wv0.w*cv.w;
                s1[bq] += wv1.x*cv.x + wv1.y*cv.y + wv1.z*cv.z + wv1.w*cv.w;
            }
        }
        #pragma unroll
        for (int off = 16; off > 0; off >>= 1) {
            #pragma unroll
            for (int bq = 0; bq < BB; bq++) {
                s0[bq] += __shfl_xor_sync(0xffffffffu, s0[bq], off);
                s1[bq] += __shfl_xor_sync(0xffffffffu, s1[bq], off);
            }
        }
        if (lane == 0) {
            const float bj0 = bias[j0];
            const float bj1 = bias[j1];
            #pragma unroll
            for (int bq = 0; bq < BB; bq++) {
                float* outc = out + (size_t)B * H + (size_t)(b0 + bq) * H;
                outc[j0] = s0[bq] + bj0;
                outc[j1] = s1[bq] + bj1;
            }
        }
    }
}

// ---------------------------------------------------------------------------
// Launch
// ---------------------------------------------------------------------------
extern "C" void kernel_launch(void* const* d_in, const int* in_sizes, int n_in,
                              void* d_out, int out_size)
{
    const float* inp_seq = (const float*)d_in[0];  // [B,S,H]
    const float* mask    = (const float*)d_in[1];  // [B,S]
    const float* query   = (const float*)d_in[2];  // [B,H]
    const float* W       = (const float*)d_in[3];  // [H,2H]
    const float* bias    = (const float*)d_in[4];  // [H]
    float* out = (float*)d_out;                    // [B*H extracted | B*H control]

    dim3 grid1(CHUNKS, B);
    attn_partial_kernel<<<grid1, 128>>>(inp_seq, mask, query, W);
    dim3 grid2(B / BB, 8);
    combine_proj_kernel<<<grid2, 256>>>(query, W, bias, out);
}

// round 15
// speedup vs baseline: 1.0137x; 1.0137x over previous
#include <cuda_runtime.h>
#include <math.h>

// Problem constants
#define B 64
#define S 4096
#define H 256
#define CHUNKS 16
#define ROWS_PER_CHUNK (S / CHUNKS)             // 256
#define WARPS 4
#define ROWS_PER_WARP (ROWS_PER_CHUNK / WARPS)  // 64 -> 2 ballot words
#define NEGC 1e30f

// Scratch: per (b, chunk): 256 acc + m + l (258 floats)
__device__ float g_scratch[B * CHUNKS * (H + 2)];

// ---------------------------------------------------------------------------
// Kernel 1: streaming online-softmax partials with mask skipping,
// 4 valid rows per iteration. (R13 config; dead W-prefetch removed)
// grid = (CHUNKS, B) = 1024 CTAs, block = 128, min 7 CTAs/SM.
// ---------------------------------------------------------------------------
__global__ void __launch_bounds__(128, 7)
attn_partial_kernel(const float* __restrict__ inp,
                    const float* __restrict__ mask,
                    const float* __restrict__ query)
{
    const int chunk = blockIdx.x;
    const int b     = blockIdx.y;
    const int tid   = threadIdx.x;
    const int w     = tid >> 5;
    const int lane  = tid & 31;

    float q[8];
    {
        const float4 q0 = *reinterpret_cast<const float4*>(query + (size_t)b * H + lane * 4);
        const float4 q1 = *reinterpret_cast<const float4*>(query + (size_t)b * H + 128 + lane * 4);
        q[0]=q0.x; q[1]=q0.y; q[2]=q0.z; q[3]=q0.w;
        q[4]=q1.x; q[5]=q1.y; q[6]=q1.z; q[7]=q1.w;
    }

    float m = -3.0e38f;
    float l = 0.0f;
    float acc[8];
    #pragma unroll
    for (int i = 0; i < 8; i++) acc[i] = 0.0f;

    const int s_base = chunk * ROWS_PER_CHUNK + w * ROWS_PER_WARP;
    const float* rowbase = inp  + ((size_t)b * S + s_base) * H + lane * 4;
    const float* mrow    = mask + (size_t)b * S + s_base;

    #pragma unroll
    for (int half = 0; half < 2; half++) {
        const float mkv = __ldcs(&mrow[half * 32 + lane]);
        unsigned bits = __ballot_sync(0xffffffffu, mkv > 0.5f);
        const float* hb = rowbase + (size_t)(half * 32) * H;

        while (bits) {
            const int r0 = __ffs(bits) - 1; bits &= bits - 1;
            const bool h1 = bits != 0;
            const int r1 = h1 ? (__ffs(bits) - 1) : r0; if (h1) bits &= bits - 1;
            const bool h2 = bits != 0;
            const int r2 = h2 ? (__ffs(bits) - 1) : r0; if (h2) bits &= bits - 1;
            const bool h3 = bits != 0;
            const int r3 = h3 ? (__ffs(bits) - 1) : r0; if (h3) bits &= bits - 1;

            const float* p0 = hb + (size_t)r0 * H;
            const float* p1 = hb + (size_t)r1 * H;
            const float* p2 = hb + (size_t)r2 * H;
            const float* p3 = hb + (size_t)r3 * H;
            const float4 a0 = __ldcs(reinterpret_cast<const float4*>(p0));
            const float4 a1 = __ldcs(reinterpret_cast<const float4*>(p0 + 128));
            const float4 b0 = __ldcs(reinterpret_cast<const float4*>(p1));
            const float4 b1 = __ldcs(reinterpret_cast<const float4*>(p1 + 128));
            const float4 c0 = __ldcs(reinterpret_cast<const float4*>(p2));
            const float4 c1 = __ldcs(reinterpret_cast<const float4*>(p2 + 128));
            const float4 e0 = __ldcs(reinterpret_cast<const float4*>(p3));
            const float4 e1 = __ldcs(reinterpret_cast<const float4*>(p3 + 128));

            float d0 = q[0]*a0.x + q[1]*a0.y + q[2]*a0.z + q[3]*a0.w
                     + q[4]*a1.x + q[5]*a1.y + q[6]*a1.z + q[7]*a1.w;
            float d1 = q[0]*b0.x + q[1]*b0.y + q[2]*b0.z + q[3]*b0.w
                     + q[4]*b1.x + q[5]*b1.y + q[6]*b1.z + q[7]*b1.w;
            float d2 = q[0]*c0.x + q[1]*c0.y + q[2]*c0.z + q[3]*c0.w
                     + q[4]*c1.x + q[5]*c1.y + q[6]*c1.z + q[7]*c1.w;
            float d3 = q[0]*e0.x + q[1]*e0.y + q[2]*e0.z + q[3]*e0.w
                     + q[4]*e1.x + q[5]*e1.y + q[6]*e1.z + q[7]*e1.w;

            #pragma unroll
            for (int off = 16; off > 0; off >>= 1) {
                d0 += __shfl_xor_sync(0xffffffffu, d0, off);
                d1 += __shfl_xor_sync(0xffffffffu, d1, off);
                d2 += __shfl_xor_sync(0xffffffffu, d2, off);
                d3 += __shfl_xor_sync(0xffffffffu, d3, off);
            }

            const float sc0 = d0;
            const float sc1 = h1 ? d1 : -3.0e38f;
            const float sc2 = h2 ? d2 : -3.0e38f;
            const float sc3 = h3 ? d3 : -3.0e38f;
            const float mn  = fmaxf(fmaxf(m, fmaxf(sc0, sc1)), fmaxf(sc2, sc3));
            const float alpha = __expf(m   - mn);
            const float p0e   = __expf(sc0 - mn);
            const float p1e   = __expf(sc1 - mn);
            const float p2e   = __expf(sc2 - mn);
            const float p3e   = __expf(sc3 - mn);
            l = l * alpha + p0e + p1e + p2e + p3e;
            acc[0] = acc[0]*alpha + p0e*a0.x + p1e*b0.x + p2e*c0.x + p3e*e0.x;
            acc[1] = acc[1]*alpha + p0e*a0.y + p1e*b0.y + p2e*c0.y + p3e*e0.y;
            acc[2] = acc[2]*alpha + p0e*a0.z + p1e*b0.z + p2e*c0.z + p3e*e0.z;
            acc[3] = acc[3]*alpha + p0e*a0.w + p1e*b0.w + p2e*c0.w + p3e*e0.w;
            acc[4] = acc[4]*alpha + p0e*a1.x + p1e*b1.x + p2e*c1.x + p3e*e1.x;
            acc[5] = acc[5]*alpha + p0e*a1.y + p1e*b1.y + p2e*c1.y + p3e*e1.y;
            acc[6] = acc[6]*alpha + p0e*a1.z + p1e*b1.z + p2e*c1.z + p3e*e1.z;
            acc[7] = acc[7]*alpha + p0e*a1.w + p1e*b1.w + p2e*c1.w + p3e*e1.w;
            m = mn;
        }
    }

    __shared__ float sm_m[WARPS];
    __shared__ float sm_l[WARPS];
    __shared__ float sm_acc[WARPS * H];

    if (lane == 0) { sm_m[w] = m; sm_l[w] = l; }
    #pragma unroll
    for (int i = 0; i < 4; i++) {
        sm_acc[w * H + lane * 4 + i]       = acc[i];
        sm_acc[w * H + 128 + lane * 4 + i] = acc[4 + i];
    }
    __syncthreads();

    float mb = sm_m[0];
    #pragma unroll
    for (int ww = 1; ww < WARPS; ww++) mb = fmaxf(mb, sm_m[ww]);

    float lb = 0.0f, ab0 = 0.0f, ab1 = 0.0f;
    #pragma unroll
    for (int ww = 0; ww < WARPS; ww++) {
        const float e = __expf(sm_m[ww] - mb);
        lb  += sm_l[ww] * e;
        ab0 += sm_acc[ww * H + tid] * e;
        ab1 += sm_acc[ww * H + tid + 128] * e;
    }

    float* dst = g_scratch + ((size_t)(b * CHUNKS + chunk)) * (H + 2);
    dst[tid]       = ab0;
    dst[tid + 128] = ab1;
    if (tid == 0) { dst[H] = mb; dst[H + 1] = lb; }
}

// ---------------------------------------------------------------------------
// Kernel 2: fused combine + projection, warp-per-output. (R13 shape)
// grid = (B, 8) = 512 CTAs, block = 256 (8 warps); thread t combines one h.
// W is L2-prefetched HERE (by==0 CTAs), overlapping phase A's DRAM chain.
// Phase A's l-term loads are hoisted alongside msv (one MLP batch).
// ---------------------------------------------------------------------------
__global__ void __launch_bounds__(256)
combine_proj_kernel(const float* __restrict__ query,
                    const float* __restrict__ W,
                    const float* __restrict__ bias,
                    float* __restrict__ out)
{
    const int b    = blockIdx.x;
    const int by   = blockIdx.y;
    const int t    = threadIdx.x;
    const int w    = t >> 5;
    const int lane = t & 31;

    __shared__ float conc[2 * H];

    // Warm W into L2 NOW — overlaps the phase-A scratch-load latency below.
    if (by == 0) {
        const int nlines = (H * 2 * H * 4) / 128;   // 4096
        for (int line = t; line < nlines; line += 256 * 8) {
            // spread: each of 64 (by==0) CTAs covers interleaved lines
            const int idx = line + (b & 7) * 256;   // b in [0,64): 8-way interleave
            if (idx < nlines) {
                const char* p = reinterpret_cast<const char*>(W) + (size_t)idx * 128;
                asm volatile("prefetch.global.L2 [%0];" :: "l"(p));
            }
        }
    }

    const int j_base = by * 32 + w * 4;

    // Prefetch W rows for the first j-pair into registers (overlaps phase A)
    const float4* w0p = reinterpret_cast<const float4*>(W + (size_t)(j_base + 0) * (2 * H)) + lane;
    const float4* w1p = reinterpret_cast<const float4*>(W + (size_t)(j_base + 1) * (2 * H)) + lane;
    float4 w0r[4], w1r[4];
    #pragma unroll
    for (int k = 0; k < 4; k++) { w0r[k] = w0p[k * 32]; w1r[k] = w1p[k * 32]; }

    // --- Phase A: all 48 loads issued as one batch (msv, lv, av independent) ---
    const float* base = g_scratch + (size_t)b * CHUNKS * (H + 2);

    float msv[CHUNKS], lv[CHUNKS], av[CHUNKS];
    #pragma unroll
    for (int c = 0; c < CHUNKS; c++) {
        msv[c] = base[c * (H + 2) + H];
        lv[c]  = base[c * (H + 2) + H + 1];
        av[c]  = base[c * (H + 2) + t];
    }

    float m = -3.0e38f;
    #pragma unroll
    for (int c = 0; c < CHUNKS; c++) m = fmaxf(m, msv[c]);

    float l = 0.0f, a = 0.0f;
    #pragma unroll
    for (int c = 0; c < CHUNKS; c++) {
        const float e = __expf(msv[c] - m);
        l += lv[c] * e;
        a += av[c] * e;
    }

    const float ext = a / l;
    if (by == 0) out[(size_t)b * H + t] = ext;   // extracted_msg (once)
    conc[t]     = query[(size_t)b * H + t];
    conc[H + t] = ext;
    __syncthreads();

    float* outc = out + (size_t)B * H + (size_t)b * H;

    // --- Phase B pair 0: from prefetched registers ---
    {
        float s0 = 0.0f, s1 = 0.0f;
        #pragma unroll
        for (int k = 0; k < 4; k++) {
            const float4 cv = *reinterpret_cast<const float4*>(conc + (k * 32 + lane) * 4);
            s0 += w0r[k].x*cv.x + w0r[k].y*cv.y + w0r[k].z*cv.z + w0r[k].w*cv.w;
            s1 += w1r[k].x*cv.x + w1r[k].y*cv.y + w1r[k].z*cv.z + w1r[k].w*cv.w;
        }
        #pragma unroll
        for (int off = 16; off > 0; off >>= 1) {
            s0 += __shfl_xor_sync(0xffffffffu, s0, off);
            s1 += __shfl_xor_sync(0xffffffffu, s1, off);
        }
        if (lane == 0) {
            outc[j_base + 0] = s0 + bias[j_base + 0];
            outc[j_base + 1] = s1 + bias[j_base + 1];
        }
    }
    // --- Phase B pair 1 ---
    {
        const int j0 = j_base + 2;
        const int j1 = j_base + 3;
        const float4* w2p = reinterpret_cast<const float4*>(W + (size_t)j0 * (2 * H)) + lane;
        const float4* w3p = reinterpret_cast<const float4*>(W + (size_t)j1 * (2 * H)) + lane;

        float s0 = 0.0f, s1 = 0.0f;
        #pragma unroll
        for (int k = 0; k < 4; k++) {
            const float4 wv0 = w2p[k * 32];
            const float4 wv1 = w3p[k * 32];
            const float4 cv  = *reinterpret_cast<const float4*>(conc + (k * 32 + lane) * 4);
            s0 += wv0.x*cv.x + wv0.y*cv.y + wv0.z*cv.z + wv0.w*cv.w;
            s1 += wv1.x*cv.x + wv1.y*cv.y + wv1.z*cv.z + wv1.w*cv.w;
        }
        #pragma unroll
        for (int off = 16; off > 0; off >>= 1) {
            s0 += __shfl_xor_sync(0xffffffffu, s0, off);
            s1 += __shfl_xor_sync(0xffffffffu, s1, off);
        }
        if (lane == 0) {
            outc[j0] = s0 + bias[j0];
            outc[j1] = s1 + bias[j1];
        }
    }
}

// ---------------------------------------------------------------------------
// Launch
// ---------------------------------------------------------------------------
extern "C" void kernel_launch(void* const* d_in, const int* in_sizes, int n_in,
                              void* d_out, int out_size)
{
    const float* inp_seq = (const float*)d_in[0];  // [B,S,H]
    const float* mask    = (const float*)d_in[1];  // [B,S]
    const float* query   = (const float*)d_in[2];  // [B,H]
    const float* W       = (const float*)d_in[3];  // [H,2H]
    const float* bias    = (const float*)d_in[4];  // [H]
    float* out = (float*)d_out;                    // [B*H extracted | B*H control]

    dim3 grid1(CHUNKS, B);
    attn_partial_kernel<<<grid1, 128>>>(inp_seq, mask, query);
    dim3 grid2(B, 8);
    combine_proj_kernel<<<grid2, 256>>>(query, W, bias, out);
}

// round 16
// speedup vs baseline: 1.0463x; 1.0322x over previous
#include <cuda_runtime.h>
#include <math.h>

// Problem constants
#define B 64
#define S 4096
#define H 256
#define CHUNKS 16
#define ROWS_PER_CHUNK (S / CHUNKS)             // 256
#define WARPS 4
#define NEGC 1e30f

// Scratch: per (b, chunk): 256 acc + m + l (258 floats)
__device__ float g_scratch[B * CHUNKS * (H + 2)];

// ---------------------------------------------------------------------------
// Kernel 1: streaming online-softmax partials with mask skipping AND
// intra-CTA load balancing: valid row indices are compacted into shared
// memory (deterministic popcount-prefix order) and consumed round-robin in
// 4-row groups, so warp-to-warp imbalance is <=4 rows instead of +-12
// (Binomial tail). grid = (CHUNKS, B) = 1024 CTAs, block = 128, 7 CTAs/SM.
// ---------------------------------------------------------------------------
__global__ void __launch_bounds__(128, 7)
attn_partial_kernel(const float* __restrict__ inp,
                    const float* __restrict__ mask,
                    const float* __restrict__ query)
{
    const int chunk = blockIdx.x;
    const int b     = blockIdx.y;
    const int tid   = threadIdx.x;
    const int w     = tid >> 5;
    const int lane  = tid & 31;

    __shared__ unsigned       sh_bm[8];
    __shared__ unsigned short sh_idx[ROWS_PER_CHUNK];
    __shared__ float sm_m[WARPS];
    __shared__ float sm_l[WARPS];
    __shared__ float sm_acc[WARPS * H];

    // ---- Build valid-row bitmap (256 rows -> 8 ballot words) ----
    const float* mrow = mask + (size_t)b * S + chunk * ROWS_PER_CHUNK;
    const float mk0 = __ldcs(&mrow[tid]);
    const float mk1 = __ldcs(&mrow[tid + 128]);
    const unsigned bal0 = __ballot_sync(0xffffffffu, mk0 > 0.5f);
    const unsigned bal1 = __ballot_sync(0xffffffffu, mk1 > 0.5f);
    if (lane == 0) { sh_bm[w] = bal0; sh_bm[4 + w] = bal1; }

    float q[8];
    {
        const float4 q0 = *reinterpret_cast<const float4*>(query + (size_t)b * H + lane * 4);
        const float4 q1 = *reinterpret_cast<const float4*>(query + (size_t)b * H + 128 + lane * 4);
        q[0]=q0.x; q[1]=q0.y; q[2]=q0.z; q[3]=q0.w;
        q[4]=q1.x; q[5]=q1.y; q[6]=q1.z; q[7]=q1.w;
    }
    __syncthreads();

    // ---- Deterministic compaction: ascending row order ----
    unsigned words[8];
    int off[8];
    int count = 0;
    #pragma unroll
    for (int j = 0; j < 8; j++) {
        words[j] = sh_bm[j];
        off[j]   = count;
        count   += __popc(words[j]);
    }
    const unsigned lmask = (1u << lane) - 1u;
    // row tid lives in word w at bit lane; row tid+128 in word 4+w.
    if ((words[w] >> lane) & 1u)
        sh_idx[off[w] + __popc(words[w] & lmask)] = (unsigned short)tid;
    if ((words[4 + w] >> lane) & 1u)
        sh_idx[off[4 + w] + __popc(words[4 + w] & lmask)] = (unsigned short)(tid + 128);
    __syncthreads();

    // ---- Main loop: warps consume 4-row groups round-robin ----
    float m = -3.0e38f;
    float l = 0.0f;
    float acc[8];
    #pragma unroll
    for (int i = 0; i < 8; i++) acc[i] = 0.0f;

    const float* rowbase = inp + ((size_t)b * S + chunk * ROWS_PER_CHUNK) * H + lane * 4;

    for (int base = w * 4; base < count; base += 4 * WARPS) {
        const int  r0 = sh_idx[base];
        const bool h1 = base + 1 < count;
        const bool h2 = base + 2 < count;
        const bool h3 = base + 3 < count;
        const int  r1 = h1 ? sh_idx[base + 1] : r0;
        const int  r2 = h2 ? sh_idx[base + 2] : r0;
        const int  r3 = h3 ? sh_idx[base + 3] : r0;

        const float* p0 = rowbase + (size_t)r0 * H;
        const float* p1 = rowbase + (size_t)r1 * H;
        const float* p2 = rowbase + (size_t)r2 * H;
        const float* p3 = rowbase + (size_t)r3 * H;
        const float4 a0 = __ldcs(reinterpret_cast<const float4*>(p0));
        const float4 a1 = __ldcs(reinterpret_cast<const float4*>(p0 + 128));
        const float4 b0 = __ldcs(reinterpret_cast<const float4*>(p1));
        const float4 b1 = __ldcs(reinterpret_cast<const float4*>(p1 + 128));
        const float4 c0 = __ldcs(reinterpret_cast<const float4*>(p2));
        const float4 c1 = __ldcs(reinterpret_cast<const float4*>(p2 + 128));
        const float4 e0 = __ldcs(reinterpret_cast<const float4*>(p3));
        const float4 e1 = __ldcs(reinterpret_cast<const float4*>(p3 + 128));

        float d0 = q[0]*a0.x + q[1]*a0.y + q[2]*a0.z + q[3]*a0.w
                 + q[4]*a1.x + q[5]*a1.y + q[6]*a1.z + q[7]*a1.w;
        float d1 = q[0]*b0.x + q[1]*b0.y + q[2]*b0.z + q[3]*b0.w
                 + q[4]*b1.x + q[5]*b1.y + q[6]*b1.z + q[7]*b1.w;
        float d2 = q[0]*c0.x + q[1]*c0.y + q[2]*c0.z + q[3]*c0.w
                 + q[4]*c1.x + q[5]*c1.y + q[6]*c1.z + q[7]*c1.w;
        float d3 = q[0]*e0.x + q[1]*e0.y + q[2]*e0.z + q[3]*e0.w
                 + q[4]*e1.x + q[5]*e1.y + q[6]*e1.z + q[7]*e1.w;

        #pragma unroll
        for (int off2 = 16; off2 > 0; off2 >>= 1) {
            d0 += __shfl_xor_sync(0xffffffffu, d0, off2);
            d1 += __shfl_xor_sync(0xffffffffu, d1, off2);
            d2 += __shfl_xor_sync(0xffffffffu, d2, off2);
            d3 += __shfl_xor_sync(0xffffffffu, d3, off2);
        }

        const float sc0 = d0;
        const float sc1 = h1 ? d1 : -3.0e38f;
        const float sc2 = h2 ? d2 : -3.0e38f;
        const float sc3 = h3 ? d3 : -3.0e38f;
        const float mn  = fmaxf(fmaxf(m, fmaxf(sc0, sc1)), fmaxf(sc2, sc3));
        const float alpha = __expf(m   - mn);
        const float p0e   = __expf(sc0 - mn);
        const float p1e   = __expf(sc1 - mn);
        const float p2e   = __expf(sc2 - mn);
        const float p3e   = __expf(sc3 - mn);
        l = l * alpha + p0e + p1e + p2e + p3e;
        acc[0] = acc[0]*alpha + p0e*a0.x + p1e*b0.x + p2e*c0.x + p3e*e0.x;
        acc[1] = acc[1]*alpha + p0e*a0.y + p1e*b0.y + p2e*c0.y + p3e*e0.y;
        acc[2] = acc[2]*alpha + p0e*a0.z + p1e*b0.z + p2e*c0.z + p3e*e0.z;
        acc[3] = acc[3]*alpha + p0e*a0.w + p1e*b0.w + p2e*c0.w + p3e*e0.w;
        acc[4] = acc[4]*alpha + p0e*a1.x + p1e*b1.x + p2e*c1.x + p3e*e1.x;
        acc[5] = acc[5]*alpha + p0e*a1.y + p1e*b1.y + p2e*c1.y + p3e*e1.y;
        acc[6] = acc[6]*alpha + p0e*a1.z + p1e*b1.z + p2e*c1.z + p3e*e1.z;
        acc[7] = acc[7]*alpha + p0e*a1.w + p1e*b1.w + p2e*c1.w + p3e*e1.w;
        m = mn;
    }

    // ---- Block-level combine of 4 warp partials ----
    if (lane == 0) { sm_m[w] = m; sm_l[w] = l; }
    #pragma unroll
    for (int i = 0; i < 4; i++) {
        sm_acc[w * H + lane * 4 + i]       = acc[i];
        sm_acc[w * H + 128 + lane * 4 + i] = acc[4 + i];
    }
    __syncthreads();

    float mb = sm_m[0];
    #pragma unroll
    for (int ww = 1; ww < WARPS; ww++) mb = fmaxf(mb, sm_m[ww]);

    float lb = 0.0f, ab0 = 0.0f, ab1 = 0.0f;
    #pragma unroll
    for (int ww = 0; ww < WARPS; ww++) {
        const float e = __expf(sm_m[ww] - mb);
        lb  += sm_l[ww] * e;
        ab0 += sm_acc[ww * H + tid] * e;
        ab1 += sm_acc[ww * H + tid + 128] * e;
    }

    float* dst = g_scratch + ((size_t)(b * CHUNKS + chunk)) * (H + 2);
    dst[tid]       = ab0;
    dst[tid + 128] = ab1;
    if (tid == 0) { dst[H] = mb; dst[H + 1] = lb; }
}

// ---------------------------------------------------------------------------
// Kernel 2: fused combine + projection, warp-per-output. (exact R13 shape)
// grid = (B, 8) = 512 CTAs, block = 256 (8 warps); thread t combines one h.
// ---------------------------------------------------------------------------
__global__ void __launch_bounds__(256)
combine_proj_kernel(const float* __restrict__ query,
                    const float* __restrict__ W,
                    const float* __restrict__ bias,
                    float* __restrict__ out)
{
    const int b    = blockIdx.x;
    const int by   = blockIdx.y;
    const int t    = threadIdx.x;
    const int w    = t >> 5;
    const int lane = t & 31;

    __shared__ float conc[2 * H];

    const int j_base = by * 32 + w * 4;

    // Prefetch W rows for the first j-pair into registers (overlaps phase A)
    const float4* w0p = reinterpret_cast<const float4*>(W + (size_t)(j_base + 0) * (2 * H)) + lane;
    const float4* w1p = reinterpret_cast<const float4*>(W + (size_t)(j_base + 1) * (2 * H)) + lane;
    float4 w0r[4], w1r[4];
    #pragma unroll
    for (int k = 0; k < 4; k++) { w0r[k] = w0p[k * 32]; w1r[k] = w1p[k * 32]; }

    // --- Phase A: combine the 16 chunk partials for element h = t ---
    const float* base = g_scratch + (size_t)b * CHUNKS * (H + 2);

    float m = -3.0e38f;
    float msv[CHUNKS];
    #pragma unroll
    for (int c = 0; c < CHUNKS; c++) {
        msv[c] = base[c * (H + 2) + H];
        m = fmaxf(m, msv[c]);
    }

    float l = 0.0f, a = 0.0f;
    #pragma unroll
    for (int c = 0; c < CHUNKS; c++) {
        const float e = __expf(msv[c] - m);
        l += base[c * (H + 2) + H + 1] * e;
        a += base[c * (H + 2) + t] * e;
    }

    const float ext = a / l;
    if (by == 0) out[(size_t)b * H + t] = ext;   // extracted_msg (once)
    conc[t]     = query[(size_t)b * H + t];
    conc[H + t] = ext;
    __syncthreads();

    float* outc = out + (size_t)B * H + (size_t)b * H;

    // --- Phase B pair 0: from prefetched registers ---
    {
        float s0 = 0.0f, s1 = 0.0f;
        #pragma unroll
        for (int k = 0; k < 4; k++) {
            const float4 cv = *reinterpret_cast<const float4*>(conc + (k * 32 + lane) * 4);
            s0 += w0r[k].x*cv.x + w0r[k].y*cv.y + w0r[k].z*cv.z + w0r[k].w*cv.w;
            s1 += w1r[k].x*cv.x + w1r[k].y*cv.y + w1r[k].z*cv.z + w1r[k].w*cv.w;
        }
        #pragma unroll
        for (int off = 16; off > 0; off >>= 1) {
            s0 += __shfl_xor_sync(0xffffffffu, s0, off);
            s1 += __shfl_xor_sync(0xffffffffu, s1, off);
        }
        if (lane == 0) {
            outc[j_base + 0] = s0 + bias[j_base + 0];
            outc[j_base + 1] = s1 + bias[j_base + 1];
        }
    }
    // --- Phase B pair 1 ---
    {
        const int j0 = j_base + 2;
        const int j1 = j_base + 3;
        const float4* w2p = reinterpret_cast<const float4*>(W + (size_t)j0 * (2 * H)) + lane;
        const float4* w3p = reinterpret_cast<const float4*>(W + (size_t)j1 * (2 * H)) + lane;

        float s0 = 0.0f, s1 = 0.0f;
        #pragma unroll
        for (int k = 0; k < 4; k++) {
            const float4 wv0 = w2p[k * 32];
            const float4 wv1 = w3p[k * 32];
            const float4 cv  = *reinterpret_cast<const float4*>(conc + (k * 32 + lane) * 4);
            s0 += wv0.x*cv.x + wv0.y*cv.y + wv0.z*cv.z + wv0.w*cv.w;
            s1 += wv1.x*cv.x + wv1.y*cv.y + wv1.z*cv.z + wv1.w*cv.w;
        }
        #pragma unroll
        for (int off = 16; off > 0; off >>= 1) {
            s0 += __shfl_xor_sync(0xffffffffu, s0, off);
            s1 += __shfl_xor_sync(0xffffffffu, s1, off);
        }
        if (lane == 0) {
            outc[j0] = s0 + bias[j0];
            outc[j1] = s1 + bias[j1];
        }
    }
}

// ---------------------------------------------------------------------------
// Launch
// ---------------------------------------------------------------------------
extern "C" void kernel_launch(void* const* d_in, const int* in_sizes, int n_in,
                              void* d_out, int out_size)
{
    const float* inp_seq = (const float*)d_in[0];  // [B,S,H]
    const float* mask    = (const float*)d_in[1];  // [B,S]
    const float* query   = (const float*)d_in[2];  // [B,H]
    const float* W       = (const float*)d_in[3];  // [H,2H]
    const float* bias    = (const float*)d_in[4];  // [H]
    float* out = (float*)d_out;                    // [B*H extracted | B*H control]

    dim3 grid1(CHUNKS, B);
    attn_partial_kernel<<<grid1, 128>>>(inp_seq, mask, query);
    dim3 grid2(B, 8);
    combine_proj_kernel<<<grid2, 256>>>(query, W, bias, out);
}